// round 5
// baseline (speedup 1.0000x reference)
#include <cuda_runtime.h>
#include <cstdint>

#define NB   512
#define CCH  32
#define LL   1024
#define ASTR (CCH*LL)          // 32768: stride between consecutive n rows
#define BN_EPS 1e-5f

// 64 MB each — scratch activations between layers (allocation-free per rules)
__device__ float g_h1[NB*CCH*LL];
__device__ float g_h2[NB*CCH*LL];

__device__ __forceinline__ uint32_t f2tf32(float f) {
    uint32_t u;
    asm volatile("cvt.rna.tf32.f32 %0, %1;" : "=r"(u) : "f"(f));
    return u;
}

__device__ __forceinline__ void mma_tf32(float* d,
                                         const uint32_t* a, const uint32_t* b) {
    asm volatile(
        "mma.sync.aligned.m16n8k8.row.col.f32.tf32.tf32.f32 "
        "{%0,%1,%2,%3}, {%4,%5,%6,%7}, {%8,%9}, {%0,%1,%2,%3};"
        : "+f"(d[0]), "+f"(d[1]), "+f"(d[2]), "+f"(d[3])
        : "r"(a[0]), "r"(a[1]), "r"(a[2]), "r"(a[3]), "r"(b[0]), "r"(b[1]));
}

__device__ __forceinline__ void cp16(uint32_t saddr, const float* g) {
    asm volatile("cp.async.ca.shared.global [%0], [%1], 16;" :: "r"(saddr), "l"(g));
}

// ---------------------------------------------------------------------------
// GEMM: out[n, c, m] = act( sum_k A[n, c, k] * W[c, layer, m, k] + bias[c, layer, m] )
// CTA tile 128(M=n) x 128(N=m), K-chunk 16, double-buffered cp.async.
// Warps 2(M) x 4(N): warp tile 64x32 via m16n8k8 tf32 mma (4 x 4 frags).
// ---------------------------------------------------------------------------
template <bool RELU>
__global__ __launch_bounds__(256, 2)
void gemm_layer(const float* __restrict__ A, const float* __restrict__ W,
                const float* __restrict__ bias, float* __restrict__ out,
                int layer)
{
    __shared__ float sA[2][128][20];   // [stage][n-row][k] pad->20 (conflict-free)
    __shared__ float sB[2][128][20];   // [stage][m-row][k]

    const int tid  = threadIdx.x;
    const int warp = tid >> 5;
    const int lane = tid & 31;
    const int g    = lane >> 2;        // groupID 0..7
    const int tg   = lane & 3;         // threadID in group 0..3
    const int wm   = warp >> 2;        // 0..1  (M dir)
    const int wn   = warp & 3;         // 0..3  (N dir)

    const int bx = blockIdx.x;         // M tile: n-rows      (4)
    const int by = blockIdx.y;         // N tile: m-cols      (8)
    const int c  = blockIdx.z;         // channel             (32)

    const float* Abase = A + (long)(bx * 128) * ASTR + c * LL;
    const float* Wbase = W + ((long)(c * 3 + layer) * LL + by * 128) * LL;

    // cp.async assignments: 512 float4 per tile per stage, 2 per thread
    const int i0 = tid, i1 = tid + 256;
    const int ar0 = i0 >> 2, aq0 = (i0 & 3) * 4;
    const int ar1 = i1 >> 2, aq1 = (i1 & 3) * 4;

    uint32_t sA0a = (uint32_t)__cvta_generic_to_shared(&sA[0][ar0][aq0]);
    uint32_t sA1a = (uint32_t)__cvta_generic_to_shared(&sA[0][ar1][aq1]);
    uint32_t sB0a = (uint32_t)__cvta_generic_to_shared(&sB[0][ar0][aq0]);
    uint32_t sB1a = (uint32_t)__cvta_generic_to_shared(&sB[0][ar1][aq1]);
    const uint32_t stgoff = (uint32_t)(128 * 20 * sizeof(float));

    float acc[4][4][4];
#pragma unroll
    for (int i = 0; i < 4; i++)
#pragma unroll
        for (int j = 0; j < 4; j++)
#pragma unroll
            for (int r = 0; r < 4; r++) acc[i][j][r] = 0.f;

    auto issue_stage = [&](int st, int k0) {
        uint32_t so = st ? stgoff : 0u;
        cp16(sA0a + so, Abase + (long)ar0 * ASTR + k0 + aq0);
        cp16(sA1a + so, Abase + (long)ar1 * ASTR + k0 + aq1);
        cp16(sB0a + so, Wbase + (long)ar0 * LL + k0 + aq0);
        cp16(sB1a + so, Wbase + (long)ar1 * LL + k0 + aq1);
        asm volatile("cp.async.commit_group;");
    };

    issue_stage(0, 0);

    const int NT = LL / 16;   // 64 k-chunks
    for (int kt = 0; kt < NT; ++kt) {
        if (kt + 1 < NT) {
            issue_stage((kt + 1) & 1, (kt + 1) * 16);
            asm volatile("cp.async.wait_group 1;");
        } else {
            asm volatile("cp.async.wait_group 0;");
        }
        __syncthreads();

        const int st = kt & 1;
#pragma unroll
        for (int ks = 0; ks < 16; ks += 8) {
            uint32_t afr[4][4];
#pragma unroll
            for (int fm = 0; fm < 4; fm++) {
                const int r = wm * 64 + fm * 16 + g;
                afr[fm][0] = f2tf32(sA[st][r    ][ks + tg    ]);
                afr[fm][1] = f2tf32(sA[st][r + 8][ks + tg    ]);
                afr[fm][2] = f2tf32(sA[st][r    ][ks + tg + 4]);
                afr[fm][3] = f2tf32(sA[st][r + 8][ks + tg + 4]);
            }
            uint32_t bfr[4][2];
#pragma unroll
            for (int fn = 0; fn < 4; fn++) {
                const int rn = wn * 32 + fn * 8 + g;
                bfr[fn][0] = f2tf32(sB[st][rn][ks + tg    ]);
                bfr[fn][1] = f2tf32(sB[st][rn][ks + tg + 4]);
            }
#pragma unroll
            for (int fm = 0; fm < 4; fm++)
#pragma unroll
                for (int fn = 0; fn < 4; fn++)
                    mma_tf32(acc[fm][fn], afr[fm], bfr[fn]);
        }
        __syncthreads();
    }

    // Epilogue: bias (+ReLU), float2 stores into (N, C, L) layout
    const float* bp = bias + (long)(c * 3 + layer) * LL + by * 128;
#pragma unroll
    for (int fm = 0; fm < 4; fm++) {
        const int n0 = bx * 128 + wm * 64 + fm * 16 + g;
#pragma unroll
        for (int fn = 0; fn < 4; fn++) {
            const int ml = wn * 32 + fn * 8 + 2 * tg;
            const int mg = by * 128 + ml;
            const float b0 = bp[ml], b1 = bp[ml + 1];
            float v0 = acc[fm][fn][0] + b0;
            float v1 = acc[fm][fn][1] + b1;
            float v2 = acc[fm][fn][2] + b0;
            float v3 = acc[fm][fn][3] + b1;
            if (RELU) {
                v0 = fmaxf(v0, 0.f); v1 = fmaxf(v1, 0.f);
                v2 = fmaxf(v2, 0.f); v3 = fmaxf(v3, 0.f);
            }
            const long o = (long)n0 * ASTR + c * LL + mg;
            *reinterpret_cast<float2*>(out + o)            = make_float2(v0, v1);
            *reinterpret_cast<float2*>(out + o + 8L * ASTR) = make_float2(v2, v3);
        }
    }
}

// ---------------------------------------------------------------------------
// Training-mode BatchNorm over n (biased var), in-place normalize.
// One thread per (c, m) column; two passes (2nd pass is L2-resident).
// ---------------------------------------------------------------------------
__global__ void bn_normalize(float* __restrict__ h,
                             const float* __restrict__ gamma,
                             const float* __restrict__ beta, int j)
{
    const int idx = blockIdx.x * blockDim.x + threadIdx.x;   // 0..32767
    const int c = idx >> 10;
    const int m = idx & 1023;
    float* p = h + (long)c * LL + m;

    float s = 0.f, sq = 0.f;
#pragma unroll 8
    for (int n = 0; n < NB; n++) {
        const float v = p[(long)n * ASTR];
        s += v; sq += v * v;
    }
    const float mean = s * (1.f / NB);
    const float var  = sq * (1.f / NB) - mean * mean;   // biased
    const long  go   = (long)(c * 2 + j) * LL + m;
    const float sc   = gamma[go] * rsqrtf(var + BN_EPS);
    const float sh   = beta[go] - mean * sc;

#pragma unroll 8
    for (int n = 0; n < NB; n++) {
        const long o = (long)n * ASTR;
        p[o] = fmaf(p[o], sc, sh);
    }
}

extern "C" void kernel_launch(void* const* d_in, const int* in_sizes, int n_in,
                              void* d_out, int out_size)
{
    const float* x     = (const float*)d_in[0];
    const float* W     = (const float*)d_in[1];
    const float* b     = (const float*)d_in[2];
    const float* gamma = (const float*)d_in[3];
    const float* beta  = (const float*)d_in[4];
    float* out = (float*)d_out;

    float *h1 = nullptr, *h2 = nullptr;
    cudaGetSymbolAddress((void**)&h1, g_h1);
    cudaGetSymbolAddress((void**)&h2, g_h2);

    dim3 grid(4, 8, 32), blk(256);

    gemm_layer<true ><<<grid, blk>>>(x,  W, b, h1,  0);
    bn_normalize      <<<128,  256>>>(h1, gamma, beta, 0);
    gemm_layer<true ><<<grid, blk>>>(h1, W, b, h2,  1);
    bn_normalize      <<<128,  256>>>(h2, gamma, beta, 1);
    gemm_layer<false><<<grid, blk>>>(h2, W, b, out, 2);
}

// round 11
// speedup vs baseline: 1.1427x; 1.1427x over previous
#include <cuda_runtime.h>
#include <cstdint>

#define NB   512
#define CCH  32
#define LL   1024
#define ASTR (CCH*LL)            // 32768 floats between consecutive n rows
#define BN_EPS 1e-5f

// ---- GEMM tiling: CTA 128(n) x 128(m), K-chunk 16, 4-stage cp.async ring ----
#define BK        16
#define NSTAGE    4
#define ROWPAD    20                         // floats per smem row (conflict-free)
#define A_STG_F   (128*ROWPAD)               // 2560 floats per stage
#define STG_BYTES (A_STG_F*4)                // 10240
#define B_BASE_BYTES (NSTAGE*STG_BYTES)      // 40960
#define SMEM_BYTES (2*NSTAGE*STG_BYTES)      // 81920

// Scratch (allocation-free per harness rules)
__device__ float g_h1[NB*CCH*LL];
__device__ float g_h2[NB*CCH*LL];
__device__ float g_scale[CCH*LL];
__device__ float g_shift[CCH*LL];

// ---------------------------------------------------------------------------
// helpers
// ---------------------------------------------------------------------------
__device__ __forceinline__ uint32_t smem_u32(const void* p) {
    uint32_t a;
    asm("{ .reg .u64 t; cvta.to.shared.u64 t, %1; cvt.u32.u64 %0, t; }"
        : "=r"(a) : "l"(p));
    return a;
}
__device__ __forceinline__ uint32_t f2tf32(float f) {
    uint32_t u;
    asm volatile("cvt.rna.tf32.f32 %0, %1;" : "=r"(u) : "f"(f));
    return u;
}
__device__ __forceinline__ uint32_t cvtbits(uint32_t u) {
    return f2tf32(__uint_as_float(u));
}
__device__ __forceinline__ void cp16(uint32_t s, const float* g) {
    asm volatile("cp.async.ca.shared.global [%0], [%1], 16;" :: "r"(s), "l"(g));
}
__device__ __forceinline__ void ldsm4(uint32_t* r, uint32_t addr) {
    asm volatile("ldmatrix.sync.aligned.m8n8.x4.shared.b16 {%0,%1,%2,%3}, [%4];"
                 : "=r"(r[0]), "=r"(r[1]), "=r"(r[2]), "=r"(r[3]) : "r"(addr));
}
__device__ __forceinline__ void mma_tf32(float* d, const uint32_t* a,
                                         const uint32_t b0, const uint32_t b1) {
    asm volatile(
        "mma.sync.aligned.m16n8k8.row.col.f32.tf32.tf32.f32 "
        "{%0,%1,%2,%3}, {%4,%5,%6,%7}, {%8,%9}, {%0,%1,%2,%3};"
        : "+f"(d[0]), "+f"(d[1]), "+f"(d[2]), "+f"(d[3])
        : "r"(a[0]), "r"(a[1]), "r"(a[2]), "r"(a[3]), "r"(b0), "r"(b1));
}

// ---------------------------------------------------------------------------
// GEMM: out[n, c, m] = act( sum_k A[n,c,k] * W[c,layer,m,k] + bias[c,layer,m] )
// 256 threads: warps 2(M-n) x 4(N-m), warp tile 64x32, frags via ldmatrix.x4.
// CVTA: round A fragments to tf32 (skip when A pre-rounded by bn_norm).
// ---------------------------------------------------------------------------
template <bool RELU, bool CVTA>
__global__ __launch_bounds__(256, 2)
void gemm_lm(const float* __restrict__ A, const float* __restrict__ W,
             const float* __restrict__ bias, float* __restrict__ out, int layer)
{
    extern __shared__ float smem[];
    const uint32_t sbase = smem_u32(smem);

    const int tid  = threadIdx.x;
    const int warp = tid >> 5, lane = tid & 31;
    const int g    = lane >> 2, tg = lane & 3;
    const int wm   = warp >> 2, wn = warp & 3;
    const int bx = blockIdx.x, by = blockIdx.y, c = blockIdx.z;

    const float* Ab = A + (long)(bx * 128) * ASTR + c * LL;
    const float* Wb = W + ((long)(c * 3 + layer) * LL + by * 128) * LL;

    // global->shared map: 512 float4 per operand per stage, 2 per thread
    const int r0 = tid >> 2, q0 = (tid & 3) * 4;   // rows 0..63
    const int r1 = r0 + 64;                         // rows 64..127
    const uint32_t so0 = (uint32_t)(r0 * ROWPAD + q0) * 4;
    const uint32_t so1 = (uint32_t)(r1 * ROWPAD + q0) * 4;
    const float* ag0 = Ab + (long)r0 * ASTR + q0;
    const float* ag1 = Ab + (long)r1 * ASTR + q0;
    const float* bg0 = Wb + (long)r0 * LL   + q0;
    const float* bg1 = Wb + (long)r1 * LL   + q0;

    auto load_stage = [&](int st, int k0) {
        const uint32_t ab = sbase + (uint32_t)st * STG_BYTES;
        const uint32_t bb = ab + B_BASE_BYTES;
        cp16(ab + so0, ag0 + k0);
        cp16(ab + so1, ag1 + k0);
        cp16(bb + so0, bg0 + k0);
        cp16(bb + so1, bg1 + k0);
        asm volatile("cp.async.commit_group;");
    };

    // ldmatrix per-thread sub-row address component:
    // row = base + (lane & 15), kcol = ks + 4*(lane >> 4)
    const uint32_t lrow = lane & 15, lk4 = (lane >> 4) * 4;
    const uint32_t aoff = ((uint32_t)(wm * 64 + lrow) * ROWPAD + lk4) * 4;
    const uint32_t boff = ((uint32_t)(wn * 32 + lrow) * ROWPAD + lk4) * 4;

    float acc[4][4][4];
#pragma unroll
    for (int i = 0; i < 4; i++)
#pragma unroll
        for (int j = 0; j < 4; j++)
#pragma unroll
            for (int r = 0; r < 4; r++) acc[i][j][r] = 0.f;

    load_stage(0, 0);
    load_stage(1, BK);
    load_stage(2, 2 * BK);

    const int NT = LL / BK;   // 64
#pragma unroll 1
    for (int kt = 0; kt < NT; ++kt) {
        if (kt <= NT - 3)      asm volatile("cp.async.wait_group 2;");
        else if (kt == NT - 2) asm volatile("cp.async.wait_group 1;");
        else                   asm volatile("cp.async.wait_group 0;");
        __syncthreads();   // stage kt visible to all; slot (kt-1)&3 free to refill

        if (kt + 3 < NT) load_stage((kt + 3) & 3, (kt + 3) * BK);

        const uint32_t ab = sbase + (uint32_t)(kt & 3) * STG_BYTES;
        const uint32_t bb = ab + B_BASE_BYTES;

#pragma unroll
        for (int ks = 0; ks < BK; ks += 8) {
            uint32_t af[4][4];
#pragma unroll
            for (int fm = 0; fm < 4; fm++) {
                ldsm4(af[fm], ab + aoff + (uint32_t)(fm * 16 * ROWPAD + ks) * 4);
                if (CVTA) {
#pragma unroll
                    for (int r = 0; r < 4; r++) af[fm][r] = cvtbits(af[fm][r]);
                }
            }
            uint32_t bm0[4], bm1[4];
            ldsm4(bm0, bb + boff + (uint32_t)ks * 4);                       // fn 0,1
            ldsm4(bm1, bb + boff + (uint32_t)(16 * ROWPAD + ks) * 4);       // fn 2,3
#pragma unroll
            for (int r = 0; r < 4; r++) { bm0[r] = cvtbits(bm0[r]); bm1[r] = cvtbits(bm1[r]); }

            // bfr[fn] = {b0, b1}: fn0={bm0[0],bm0[2]} fn1={bm0[1],bm0[3]}
            //                     fn2={bm1[0],bm1[2]} fn3={bm1[1],bm1[3]}
#pragma unroll
            for (int fm = 0; fm < 4; fm++) {
                mma_tf32(acc[fm][0], af[fm], bm0[0], bm0[2]);
                mma_tf32(acc[fm][1], af[fm], bm0[1], bm0[3]);
                mma_tf32(acc[fm][2], af[fm], bm1[0], bm1[2]);
                mma_tf32(acc[fm][3], af[fm], bm1[1], bm1[3]);
            }
        }
    }

    // Epilogue: bias (+ReLU), float2 stores into (N, C, L)
    const float* bp = bias + (long)(c * 3 + layer) * LL + by * 128;
#pragma unroll
    for (int fm = 0; fm < 4; fm++) {
        const int n0 = bx * 128 + wm * 64 + fm * 16 + g;
#pragma unroll
        for (int fn = 0; fn < 4; fn++) {
            const int ml = wn * 32 + fn * 8 + 2 * tg;
            const int mg = by * 128 + ml;
            const float b0 = bp[ml], b1 = bp[ml + 1];
            float v0 = acc[fm][fn][0] + b0;
            float v1 = acc[fm][fn][1] + b1;
            float v2 = acc[fm][fn][2] + b0;
            float v3 = acc[fm][fn][3] + b1;
            if (RELU) {
                v0 = fmaxf(v0, 0.f); v1 = fmaxf(v1, 0.f);
                v2 = fmaxf(v2, 0.f); v3 = fmaxf(v3, 0.f);
            }
            const long o = (long)n0 * ASTR + c * LL + mg;
            *reinterpret_cast<float2*>(out + o)             = make_float2(v0, v1);
            *reinterpret_cast<float2*>(out + o + 8L * ASTR) = make_float2(v2, v3);
        }
    }
}

// ---------------------------------------------------------------------------
// BN stats: per (c, m) mean/biased-var over n -> scale/shift.
// grid (8, 32) x 512 threads: 4 n-quarters per column, smem combine.
// ---------------------------------------------------------------------------
__global__ __launch_bounds__(512)
void bn_stats(const float* __restrict__ h, const float* __restrict__ gamma,
              const float* __restrict__ beta, int j)
{
    __shared__ float ss[4][128], sq2[4][128];
    const int m_off = threadIdx.x & 127;
    const int q     = threadIdx.x >> 7;
    const int c     = blockIdx.y;
    const int m     = blockIdx.x * 128 + m_off;
    const float* p  = h + (long)c * LL + m + (long)(q * 128) * ASTR;

    float s = 0.f, sq = 0.f;
#pragma unroll 8
    for (int n = 0; n < 128; n++) {
        const float v = p[(long)n * ASTR];
        s += v; sq += v * v;
    }
    ss[q][m_off] = s; sq2[q][m_off] = sq;
    __syncthreads();
    if (q == 0) {
        s  = ss[0][m_off] + ss[1][m_off] + ss[2][m_off] + ss[3][m_off];
        sq = sq2[0][m_off] + sq2[1][m_off] + sq2[2][m_off] + sq2[3][m_off];
        const float mean = s * (1.f / NB);
        const float var  = sq * (1.f / NB) - mean * mean;    // biased
        const long  go   = (long)(c * 2 + j) * LL + m;
        const float sc   = gamma[go] * rsqrtf(var + BN_EPS);
        g_scale[c * LL + m] = sc;
        g_shift[c * LL + m] = beta[go] - mean * sc;
    }
}

// ---------------------------------------------------------------------------
// BN normalize (in place), output rounded to tf32 (rna) so the next GEMM
// can skip the A-side cvt. float4, fully parallel.
// ---------------------------------------------------------------------------
__global__ __launch_bounds__(256)
void bn_norm(float* __restrict__ h)
{
    const long e  = ((long)blockIdx.x * 256 + threadIdx.x) * 4;
    const int cm  = (int)(e & (long)(ASTR - 1));
    float4 v  = *reinterpret_cast<float4*>(h + e);
    const float4 sc = *reinterpret_cast<const float4*>(g_scale + cm);
    const float4 sh = *reinterpret_cast<const float4*>(g_shift + cm);
    v.x = __uint_as_float(f2tf32(fmaf(v.x, sc.x, sh.x)));
    v.y = __uint_as_float(f2tf32(fmaf(v.y, sc.y, sh.y)));
    v.z = __uint_as_float(f2tf32(fmaf(v.z, sc.z, sh.z)));
    v.w = __uint_as_float(f2tf32(fmaf(v.w, sc.w, sh.w)));
    *reinterpret_cast<float4*>(h + e) = v;
}

// ---------------------------------------------------------------------------
extern "C" void kernel_launch(void* const* d_in, const int* in_sizes, int n_in,
                              void* d_out, int out_size)
{
    const float* x     = (const float*)d_in[0];
    const float* W     = (const float*)d_in[1];
    const float* b     = (const float*)d_in[2];
    const float* gamma = (const float*)d_in[3];
    const float* beta  = (const float*)d_in[4];
    float* out = (float*)d_out;

    float *h1 = nullptr, *h2 = nullptr;
    cudaGetSymbolAddress((void**)&h1, g_h1);
    cudaGetSymbolAddress((void**)&h2, g_h2);

    cudaFuncSetAttribute(gemm_lm<true,  true >, cudaFuncAttributeMaxDynamicSharedMemorySize, SMEM_BYTES);
    cudaFuncSetAttribute(gemm_lm<true,  false>, cudaFuncAttributeMaxDynamicSharedMemorySize, SMEM_BYTES);
    cudaFuncSetAttribute(gemm_lm<false, false>, cudaFuncAttributeMaxDynamicSharedMemorySize, SMEM_BYTES);

    const dim3 ggrid(4, 8, 32), gblk(256);
    const dim3 sgrid(8, 32), sblk(512);
    const int  nblk = (NB * CCH * LL) / 4 / 256;   // 16384

    gemm_lm<true,  true ><<<ggrid, gblk, SMEM_BYTES>>>(x,  W, b, h1,  0);
    bn_stats<<<sgrid, sblk>>>(h1, gamma, beta, 0);
    bn_norm <<<nblk, 256>>>(h1);
    gemm_lm<true,  false><<<ggrid, gblk, SMEM_BYTES>>>(h1, W, b, h2,  1);
    bn_stats<<<sgrid, sblk>>>(h2, gamma, beta, 1);
    bn_norm <<<nblk, 256>>>(h2);
    gemm_lm<false, false><<<ggrid, gblk, SMEM_BYTES>>>(h2, W, b, out, 2);
}